// round 13
// baseline (speedup 1.0000x reference)
#include <cuda_runtime.h>
#include <cuda_bf16.h>
#include <math.h>

// AUCM pairwise margin loss, B=1024, C=128, margin=1. One launch.
//
// Math: softplus(b-a), a,b = sigmoids in (0,1), t = b-a in (-1,1):
//   softplus(t) = ln2 + t/2 + t^2/8 - t^4/192   (degree-4; ~1.5e-5 realistic
//   truncation, gate is 1e-3)
// Binomial factorization collapses the O(B^2) (pos,neg) pair sum per class
// to power sums: T_k over all rows (T_0 = 1024 free), P_k over pos rows.
//
// R13 (R12 base + issue/tail micro-cuts):
//   - 128 blocks x 256 threads; block c owns class c entirely (block-local
//     is structurally optimal: any row-split forces an inter-block moment
//     exchange costing >= the wavefront savings -- measured R7/R9/R11).
//   - 4 rows/thread, all 8 LDGs front-batched (shorter per-warp issue chain,
//     8 warps feed the L1tex wavefront pipe).
//   - P0 via popc(ballot): targets are exact {0,1} -> one fewer accumulator
//     in the shuffle tree, exact integer count.
//   - Single packed 64-bit atomicAdd carries {block count, valid count,
//     fixed-point mean sum}: data + ticket + ordering in one op; integer
//     accumulation is bit-exact across graph replays.

#define NROWS 1024
#define NCLS  128
#define NBLK  128
#define NTH   256
#define NW    (NTH / 32)     // 8 warps
#define RPT   (NROWS / NTH)  // 4 rows per thread
#define FXS   1099511627776.0   // 2^40 fixed-point scale

__device__ unsigned long long g_pack = 0ULL;

__global__ __launch_bounds__(NTH)
void aucm_kernel(const float* __restrict__ logits,
                 const float* __restrict__ targets,
                 float* __restrict__ out)
{
    const int c    = blockIdx.x;   // class
    const int tid  = threadIdx.x;
    const int warp = tid >> 5;
    const int lane = tid & 31;

    // Front-batched loads: 8 independent LDGs in flight per thread.
    float xs[RPT], tg[RPT];
#pragma unroll
    for (int r = 0; r < RPT; r++) {
        const int row = tid + r * NTH;
        xs[r] = logits [row * NCLS + c];
        tg[r] = targets[row * NCLS + c];   // exact 0.0f / 1.0f
    }

    // Power sums: T_k over my rows (k=1..4), P_k over pos rows (k=1..4),
    // P0 as an exact popcount.
    float T1 = 0.f, T2 = 0.f, T3 = 0.f, T4 = 0.f;
    float P1 = 0.f, P2 = 0.f, P3 = 0.f, P4 = 0.f;
    int   np = 0;
#pragma unroll
    for (int r = 0; r < RPT; r++) {
        const float p  = __fdividef(1.0f, 1.0f + __expf(-xs[r]));
        const float p2 = p * p, p3 = p2 * p, p4 = p2 * p2;
        T1 += p; T2 += p2; T3 += p3; T4 += p4;
        const float t = tg[r];
        np += (t > 0.5f);
        P1 = fmaf(t, p,  P1);
        P2 = fmaf(t, p2, P2);
        P3 = fmaf(t, p3, P3);
        P4 = fmaf(t, p4, P4);
    }

    // Warp tree reduction (8 float accumulators + exact int count).
#pragma unroll
    for (int off = 16; off > 0; off >>= 1) {
        T1 += __shfl_xor_sync(0xffffffffu, T1, off);
        T2 += __shfl_xor_sync(0xffffffffu, T2, off);
        T3 += __shfl_xor_sync(0xffffffffu, T3, off);
        T4 += __shfl_xor_sync(0xffffffffu, T4, off);
        P1 += __shfl_xor_sync(0xffffffffu, P1, off);
        P2 += __shfl_xor_sync(0xffffffffu, P2, off);
        P3 += __shfl_xor_sync(0xffffffffu, P3, off);
        P4 += __shfl_xor_sync(0xffffffffu, P4, off);
        np += __shfl_xor_sync(0xffffffffu, np, off);
    }

    __shared__ float s[NW][8];
    __shared__ int   sn[NW];
    if (lane == 0) {
        s[warp][0] = T1; s[warp][1] = T2; s[warp][2] = T3; s[warp][3] = T4;
        s[warp][4] = P1; s[warp][5] = P2; s[warp][6] = P3; s[warp][7] = P4;
        sn[warp] = np;
    }
    __syncthreads();
    if (tid != 0) return;

    // ---- thread 0: cross-warp sum (64 pipelined LDS) + fp32 combine ----
    float m[8];
#pragma unroll
    for (int k = 0; k < 8; k++) {
        float v = 0.0f;
#pragma unroll
        for (int w = 0; w < NW; w++) v += s[w][k];
        m[k] = v;
    }
    int npos = 0;
#pragma unroll
    for (int w = 0; w < NW; w++) npos += sn[w];

    const float Pd0 = (float)npos;
    const float Td1 = m[0], Td2 = m[1], Td3 = m[2], Td4 = m[3];
    const float Pd1 = m[4], Pd2 = m[5], Pd3 = m[6], Pd4 = m[7];
    const float B0 = (float)(NROWS - npos);
    const float B1 = Td1 - Pd1, B2 = Td2 - Pd2,
                B3 = Td3 - Pd3, B4 = Td4 - Pd4;   // neg-row power sums

    const float cnt = Pd0 * B0;
    // d_m = sum_pairs (b-a)^m via binomial; signs from (-a)^k.
    const float d1 = B1 * Pd0 - B0 * Pd1;
    const float d2 = B2 * Pd0 - 2.0f * B1 * Pd1 + B0 * Pd2;
    const float d4 = B4 * Pd0 - 4.0f * B3 * Pd1 + 6.0f * B2 * Pd2
                   - 4.0f * B1 * Pd3 + B0 * Pd4;

    const float S = 0.69314718f * cnt
                  + 0.5f * d1
                  + d2 * (1.0f / 8.0f)
                  - d4 * (1.0f / 192.0f);

    const bool ok = (cnt > 0.0f);
    const float mean = ok ? (S / cnt) : 0.0f;   // in (0, 1.32)

    // Packed contribution: [count:8][valid:8][mean fixed-point 2^40:48].
    const unsigned long long fx =
        (unsigned long long)((double)mean * FXS + 0.5);
    const unsigned long long pk =
        (1ULL << 56) | ((ok ? 1ULL : 0ULL) << 48) | fx;

    const unsigned long long old = atomicAdd(&g_pack, pk);
    if ((old >> 56) == (unsigned long long)(NBLK - 1)) {
        // Last arriver: total is in hand, no fence/reload needed.
        const unsigned long long tot = old + pk;
        const double sum = (double)(tot & ((1ULL << 48) - 1)) * (1.0 / FXS);
        const double vc  = (double)((tot >> 48) & 0xFFULL);
        out[0] = (vc > 0.0) ? (float)(sum / vc) : 0.0f;
        g_pack = 0ULL;   // reset for next graph replay (all blocks done)
    }
}

extern "C" void kernel_launch(void* const* d_in, const int* in_sizes, int n_in,
                              void* d_out, int out_size)
{
    const float* logits  = (const float*)d_in[0];
    const float* targets = (const float*)d_in[1];
    float* out = (float*)d_out;

    aucm_kernel<<<NBLK, NTH>>>(logits, targets, out);
}

// round 14
// speedup vs baseline: 1.0607x; 1.0607x over previous
#include <cuda_runtime.h>
#include <cuda_bf16.h>
#include <math.h>
#include <stdint.h>

// AUCM pairwise margin loss, B=1024, C=128, margin=1. One clustered launch.
//
// Math: softplus(b-a), a,b = sigmoids in (0,1), t = b-a in (-1,1):
//   softplus(t) = ln2 + t/2 + t^2/8 - t^4/192  (degree-4, ~1.5e-5 realistic
//   truncation; gate 1e-3). Binomial factorization -> per-class power sums
//   T_k (all rows, T_0=1024 free) and P_k (pos rows).
//
// R14: cut the L1-wavefront drain (the dominant term) with DSMEM clusters.
//   - 128 CTAs, __cluster_dims__(4): cluster g owns classes [4g,4g+4)
//     (adjacent -> share 128B lines); CTA rank q owns rows [256q, 256q+256).
//   - float4 loads: one LDG.128 covers all 4 classes -> 512 wavefronts/SM
//     (was 2048 in R12).
//   - probs/targets staged in smem; consumer threads own (class, 8 rows) ->
//     compute + shuffle identical to R12.
//   - 36-float partial-moment exchange via mapa + st.shared::cluster + ONE
//     barrier.cluster (orders remote smem stores) -- NOT the global
//     STG/fence/reload path that lost in R9/R11.
//   - Tail: per-CTA fp32 combine + single packed 64-bit atomicAdd carrying
//     {count, valid, fixed-point mean sum}; bit-exact across graph replays.

#define NROWS 1024
#define NCLS  128
#define NBLK  128
#define NTH   128
#define CSZ   4                  // cluster size = classes per cluster
#define RPQ   (NROWS / CSZ)      // 256 rows per CTA
#define NMOM  9                  // k=0: P0, 1..4: T1..T4, 5..8: P1..P4
#define FXS   1099511627776.0    // 2^40 fixed-point scale

__device__ unsigned long long g_pack = 0ULL;

__device__ __forceinline__ uint32_t smem_u32(const void* p) {
    uint32_t a;
    asm("{ .reg .u64 t; cvta.to.shared.u64 t, %1; cvt.u32.u64 %0, t; }"
        : "=r"(a) : "l"(p));
    return a;
}
__device__ __forceinline__ void st_cluster_f32(uint32_t saddr, uint32_t rank, float v) {
    asm volatile(
        "{ .reg .b32 r; mapa.shared::cluster.u32 r, %0, %1; "
        "st.shared::cluster.f32 [r], %2; }"
        :: "r"(saddr), "r"(rank), "f"(v) : "memory");
}

__global__ __launch_bounds__(NTH) __cluster_dims__(CSZ, 1, 1)
void aucm_kernel(const float* __restrict__ logits,
                 const float* __restrict__ targets,
                 float* __restrict__ out)
{
    __shared__ float sp[RPQ][CSZ];     // probs   [local row][class-in-group]
    __shared__ float sg[RPQ][CSZ];     // targets
    __shared__ float sW[4][CSZ][NMOM]; // per-warp per-class partials
    __shared__ float sPart[CSZ][NMOM]; // incoming per-rank partials (my class)

    const int tid  = threadIdx.x;
    const int g    = blockIdx.x >> 2;          // class group
    uint32_t rank;
    asm("mov.u32 %0, %%cluster_ctarank;" : "=r"(rank));
    const int base = (int)rank * RPQ;          // my row quarter

    // ---- load phase: float4 (4 classes/LDG), front-batched, sigmoid, stage ----
    const float4* l4 = (const float4*)logits;
    const float4* t4 = (const float4*)targets;
    const int r0 = base + tid, r1 = base + tid + 128;
    const float4 xa = l4[r0 * 32 + g];
    const float4 xb = l4[r1 * 32 + g];
    const float4 ta = t4[r0 * 32 + g];
    const float4 tb = t4[r1 * 32 + g];
    float4 pa, pb;
    pa.x = __fdividef(1.f, 1.f + __expf(-xa.x));
    pa.y = __fdividef(1.f, 1.f + __expf(-xa.y));
    pa.z = __fdividef(1.f, 1.f + __expf(-xa.z));
    pa.w = __fdividef(1.f, 1.f + __expf(-xa.w));
    pb.x = __fdividef(1.f, 1.f + __expf(-xb.x));
    pb.y = __fdividef(1.f, 1.f + __expf(-xb.y));
    pb.z = __fdividef(1.f, 1.f + __expf(-xb.z));
    pb.w = __fdividef(1.f, 1.f + __expf(-xb.w));
    *(float4*)&sp[tid][0]       = pa;
    *(float4*)&sp[tid + 128][0] = pb;
    *(float4*)&sg[tid][0]       = ta;
    *(float4*)&sg[tid + 128][0] = tb;
    __syncthreads();

    // ---- compute phase: thread owns class cs, 8 rows (conflict-free LDS) ----
    const int cs = tid & 3;
    const int rs = tid >> 2;
    float P0 = 0.f, T1 = 0.f, T2 = 0.f, T3 = 0.f, T4 = 0.f;
    float P1 = 0.f, P2 = 0.f, P3 = 0.f, P4 = 0.f;
#pragma unroll
    for (int r = 0; r < 8; r++) {
        const int lr = rs + 32 * r;
        const float p  = sp[lr][cs];
        const float tg = sg[lr][cs];
        const float p2 = p * p, p3 = p2 * p, p4 = p2 * p2;
        T1 += p; T2 += p2; T3 += p3; T4 += p4;
        P0 += tg;
        P1 = fmaf(tg, p,  P1);
        P2 = fmaf(tg, p2, P2);
        P3 = fmaf(tg, p3, P3);
        P4 = fmaf(tg, p4, P4);
    }

    // Reduce over rs within warp (rs in lane bits 2..4): xor 4, 8, 16.
#pragma unroll
    for (int off = 4; off <= 16; off <<= 1) {
        P0 += __shfl_xor_sync(0xffffffffu, P0, off);
        T1 += __shfl_xor_sync(0xffffffffu, T1, off);
        T2 += __shfl_xor_sync(0xffffffffu, T2, off);
        T3 += __shfl_xor_sync(0xffffffffu, T3, off);
        T4 += __shfl_xor_sync(0xffffffffu, T4, off);
        P1 += __shfl_xor_sync(0xffffffffu, P1, off);
        P2 += __shfl_xor_sync(0xffffffffu, P2, off);
        P3 += __shfl_xor_sync(0xffffffffu, P3, off);
        P4 += __shfl_xor_sync(0xffffffffu, P4, off);
    }
    const int warp = tid >> 5, lane = tid & 31;
    if (lane < CSZ) {
        float* w = &sW[warp][lane][0];
        w[0] = P0; w[1] = T1; w[2] = T2; w[3] = T3; w[4] = T4;
        w[5] = P1; w[6] = P2; w[7] = P3; w[8] = P4;
    }
    __syncthreads();

    // ---- exchange: 36 threads gather cross-warp sums, DSMEM-send to owner ----
    if (tid < CSZ * NMOM) {
        const int j = tid / NMOM;       // class slot -> destination rank j
        const int k = tid % NMOM;
        const float v = sW[0][j][k] + sW[1][j][k] + sW[2][j][k] + sW[3][j][k];
        st_cluster_f32(smem_u32(&sPart[rank][k]), (uint32_t)j, v);
    }
    // One cluster barrier: publishes the remote smem stores cluster-wide.
    asm volatile("barrier.cluster.arrive.aligned;" ::: "memory");
    asm volatile("barrier.cluster.wait.aligned;"   ::: "memory");

    if (tid != 0) return;

    // ---- tail: combine 4 rank-partials for my class, packed atomic ----
    float m[NMOM];
#pragma unroll
    for (int k = 0; k < NMOM; k++)
        m[k] = sPart[0][k] + sPart[1][k] + sPart[2][k] + sPart[3][k];

    const float Pd0 = m[0];
    const float Td1 = m[1], Td2 = m[2], Td3 = m[3], Td4 = m[4];
    const float Pd1 = m[5], Pd2 = m[6], Pd3 = m[7], Pd4 = m[8];
    const float B0 = (float)NROWS - Pd0;
    const float B1 = Td1 - Pd1, B2 = Td2 - Pd2,
                B3 = Td3 - Pd3, B4 = Td4 - Pd4;

    const float cnt = Pd0 * B0;
    const float d1 = B1 * Pd0 - B0 * Pd1;
    const float d2 = B2 * Pd0 - 2.0f * B1 * Pd1 + B0 * Pd2;
    const float d4 = B4 * Pd0 - 4.0f * B3 * Pd1 + 6.0f * B2 * Pd2
                   - 4.0f * B1 * Pd3 + B0 * Pd4;

    const float S = 0.69314718f * cnt
                  + 0.5f * d1
                  + d2 * (1.0f / 8.0f)
                  - d4 * (1.0f / 192.0f);

    const bool ok = (cnt > 0.0f);
    const float mean = ok ? (S / cnt) : 0.0f;   // in (0, 1.32)

    const unsigned long long fx =
        (unsigned long long)((double)mean * FXS + 0.5);
    const unsigned long long pk =
        (1ULL << 56) | ((ok ? 1ULL : 0ULL) << 48) | fx;

    const unsigned long long old = atomicAdd(&g_pack, pk);
    if ((old >> 56) == (unsigned long long)(NBLK - 1)) {
        const unsigned long long tot = old + pk;
        const double sum = (double)(tot & ((1ULL << 48) - 1)) * (1.0 / FXS);
        const double vc  = (double)((tot >> 48) & 0xFFULL);
        out[0] = (vc > 0.0) ? (float)(sum / vc) : 0.0f;
        g_pack = 0ULL;   // reset for next graph replay
    }
}

extern "C" void kernel_launch(void* const* d_in, const int* in_sizes, int n_in,
                              void* d_out, int out_size)
{
    const float* logits  = (const float*)d_in[0];
    const float* targets = (const float*)d_in[1];
    float* out = (float*)d_out;

    aucm_kernel<<<NBLK, NTH>>>(logits, targets, out);
}

// round 15
// speedup vs baseline: 1.0645x; 1.0036x over previous
#include <cuda_runtime.h>
#include <cuda_bf16.h>
#include <math.h>

// AUCM pairwise margin loss, B=1024, C=128, margin=1. One launch.
//
// Math: softplus(b-a), a,b = sigmoids in (0,1), t = b-a in (-1,1):
//   softplus(t) = ln2 + t/2 + t^2/8 - t^4/192   (degree-4; ~1.5e-5 realistic
//   truncation, gate is 1e-3)
// Binomial factorization collapses the O(B^2) (pos,neg) pair sum per class
// to power sums: T_k over all rows (T_0 = 1024 free), P_k over pos rows.
//
// R15 (R12 base, last micro-cuts; structure frozen — block-local classes,
// since all four cross-block exchange topologies measured slower):
//   - 128 blocks x 64 threads; block c owns class c entirely.
//   - 16 rows/thread, all 32 LDGs front-batched (per-warp MLP ~32).
//   - 2 warps: half the __syncthreads participants, cross-warp combine is
//     18 LDS instead of 36.
//   - Single packed 64-bit atomicAdd carries {block count, valid count,
//     fixed-point mean sum}: data + ticket + ordering in one op; integer
//     accumulation is bit-exact across graph replays.

#define NROWS 1024
#define NCLS  128
#define NBLK  128
#define NTH   64
#define NW    (NTH / 32)     // 2 warps
#define RPT   (NROWS / NTH)  // 16 rows per thread
#define FXS   1099511627776.0   // 2^40 fixed-point scale

__device__ unsigned long long g_pack = 0ULL;

__global__ __launch_bounds__(NTH)
void aucm_kernel(const float* __restrict__ logits,
                 const float* __restrict__ targets,
                 float* __restrict__ out)
{
    const int c    = blockIdx.x;   // class
    const int tid  = threadIdx.x;
    const int warp = tid >> 5;
    const int lane = tid & 31;

    // Front-batched loads: 32 independent LDGs in flight per thread.
    float xs[RPT], tg[RPT];
#pragma unroll
    for (int r = 0; r < RPT; r++) {
        const int row = tid + r * NTH;
        xs[r] = logits [row * NCLS + c];
        tg[r] = targets[row * NCLS + c];   // exact 0.0f / 1.0f
    }

    // Power sums: T_k over my rows (k=1..4), P_k over pos rows (k=0..4).
    float T1 = 0.f, T2 = 0.f, T3 = 0.f, T4 = 0.f;
    float P0 = 0.f, P1 = 0.f, P2 = 0.f, P3 = 0.f, P4 = 0.f;
#pragma unroll
    for (int r = 0; r < RPT; r++) {
        const float p  = __fdividef(1.0f, 1.0f + __expf(-xs[r]));
        const float p2 = p * p, p3 = p2 * p, p4 = p2 * p2;
        T1 += p; T2 += p2; T3 += p3; T4 += p4;
        const float t = tg[r];
        P0 += t;
        P1 = fmaf(t, p,  P1);
        P2 = fmaf(t, p2, P2);
        P3 = fmaf(t, p3, P3);
        P4 = fmaf(t, p4, P4);
    }

    // Warp tree reduction (9 accumulators).
#pragma unroll
    for (int off = 16; off > 0; off >>= 1) {
        T1 += __shfl_xor_sync(0xffffffffu, T1, off);
        T2 += __shfl_xor_sync(0xffffffffu, T2, off);
        T3 += __shfl_xor_sync(0xffffffffu, T3, off);
        T4 += __shfl_xor_sync(0xffffffffu, T4, off);
        P0 += __shfl_xor_sync(0xffffffffu, P0, off);
        P1 += __shfl_xor_sync(0xffffffffu, P1, off);
        P2 += __shfl_xor_sync(0xffffffffu, P2, off);
        P3 += __shfl_xor_sync(0xffffffffu, P3, off);
        P4 += __shfl_xor_sync(0xffffffffu, P4, off);
    }

    __shared__ float s[NW][9];
    if (lane == 0) {
        s[warp][0] = T1; s[warp][1] = T2; s[warp][2] = T3; s[warp][3] = T4;
        s[warp][4] = P0; s[warp][5] = P1; s[warp][6] = P2; s[warp][7] = P3;
        s[warp][8] = P4;
    }
    __syncthreads();
    if (tid != 0) return;

    // ---- thread 0: cross-warp sum (18 pipelined LDS) + fp32 combine ----
    float m[9];
#pragma unroll
    for (int k = 0; k < 9; k++)
        m[k] = s[0][k] + s[1][k];

    const float Td1 = m[0], Td2 = m[1], Td3 = m[2], Td4 = m[3];
    const float Pd0 = m[4], Pd1 = m[5], Pd2 = m[6], Pd3 = m[7], Pd4 = m[8];
    const float B0 = (float)NROWS - Pd0;
    const float B1 = Td1 - Pd1, B2 = Td2 - Pd2,
                B3 = Td3 - Pd3, B4 = Td4 - Pd4;   // neg-row power sums

    const float cnt = Pd0 * B0;
    // d_m = sum_pairs (b-a)^m via binomial; signs from (-a)^k.
    const float d1 = B1 * Pd0 - B0 * Pd1;
    const float d2 = B2 * Pd0 - 2.0f * B1 * Pd1 + B0 * Pd2;
    const float d4 = B4 * Pd0 - 4.0f * B3 * Pd1 + 6.0f * B2 * Pd2
                   - 4.0f * B1 * Pd3 + B0 * Pd4;

    const float S = 0.69314718f * cnt
                  + 0.5f * d1
                  + d2 * (1.0f / 8.0f)
                  - d4 * (1.0f / 192.0f);

    const bool ok = (cnt > 0.0f);
    const float mean = ok ? (S / cnt) : 0.0f;   // in (0, 1.32)

    // Packed contribution: [count:8][valid:8][mean fixed-point 2^40:48].
    const unsigned long long fx =
        (unsigned long long)((double)mean * FXS + 0.5);
    const unsigned long long pk =
        (1ULL << 56) | ((ok ? 1ULL : 0ULL) << 48) | fx;

    const unsigned long long old = atomicAdd(&g_pack, pk);
    if ((old >> 56) == (unsigned long long)(NBLK - 1)) {
        // Last arriver: total is in hand, no fence/reload needed.
        const unsigned long long tot = old + pk;
        const double sum = (double)(tot & ((1ULL << 48) - 1)) * (1.0 / FXS);
        const double vc  = (double)((tot >> 48) & 0xFFULL);
        out[0] = (vc > 0.0) ? (float)(sum / vc) : 0.0f;
        g_pack = 0ULL;   // reset for next graph replay (all blocks done)
    }
}

extern "C" void kernel_launch(void* const* d_in, const int* in_sizes, int n_in,
                              void* d_out, int out_size)
{
    const float* logits  = (const float*)d_in[0];
    const float* targets = (const float*)d_in[1];
    float* out = (float*)d_out;

    aucm_kernel<<<NBLK, NTH>>>(logits, targets, out);
}

// round 16
// speedup vs baseline: 1.0959x; 1.0295x over previous
#include <cuda_runtime.h>
#include <cuda_bf16.h>
#include <math.h>

// AUCM pairwise margin loss, B=1024, C=128, margin=1. One launch.
//
// Math: softplus(b-a), a,b = sigmoids in (0,1), t = b-a in (-1,1):
//   softplus(t) = ln2 + t/2 + t^2/8 - t^4/192   (degree-4; ~1.5e-5 realistic
//   truncation, gate is 1e-3)
// Binomial factorization collapses the O(B^2) (pos,neg) pair sum per class
// to power sums: T_k over all rows (T_0 = 1024 free), P_k over pos rows.
//
// R16 = R12 champion (128 blocks x 128 threads, block-local classes, packed
// 64-bit atomic tail) + two instruction cuts in the hot loop:
//   - sigmoid via HW tanh: p = 0.5*tanh(x/2)+0.5 (MUFU.TANH). Halves MUFU
//     ops vs EX2+RCP and shortens the dependency chain per p.
//   - P0 via popc(ballot): warp-uniform exact count -> one fewer accumulator
//     in the 5-stage shuffle tree.
// Config frozen by sweep: threads 64/128/256 -> 7.97/6.30/6.66 us; all four
// cross-block exchange topologies measured slower than block-local.

#define NROWS 1024
#define NCLS  128
#define NBLK  128
#define NTH   128
#define NW    (NTH / 32)     // 4 warps
#define RPT   (NROWS / NTH)  // 8 rows per thread
#define FXS   1099511627776.0   // 2^40 fixed-point scale

__device__ unsigned long long g_pack = 0ULL;

__device__ __forceinline__ float fast_sigmoid(float x) {
    float th;
    asm("tanh.approx.f32 %0, %1;" : "=f"(th) : "f"(0.5f * x));
    return fmaf(0.5f, th, 0.5f);
}

__global__ __launch_bounds__(NTH)
void aucm_kernel(const float* __restrict__ logits,
                 const float* __restrict__ targets,
                 float* __restrict__ out)
{
    const int c    = blockIdx.x;   // class
    const int tid  = threadIdx.x;
    const int warp = tid >> 5;
    const int lane = tid & 31;

    // Front-batched loads: 16 independent LDGs in flight.
    float xs[RPT], tg[RPT];
#pragma unroll
    for (int r = 0; r < RPT; r++) {
        const int row = tid + r * NTH;
        xs[r] = logits [row * NCLS + c];
        tg[r] = targets[row * NCLS + c];   // exact 0.0f / 1.0f
    }

    // Power sums: T_k over my rows (k=1..4), P_k over pos rows (k=1..4);
    // P0 as an exact warp-uniform popcount.
    float T1 = 0.f, T2 = 0.f, T3 = 0.f, T4 = 0.f;
    float P1 = 0.f, P2 = 0.f, P3 = 0.f, P4 = 0.f;
    int   np = 0;   // warp-total (uniform across lanes)
#pragma unroll
    for (int r = 0; r < RPT; r++) {
        const float p  = fast_sigmoid(xs[r]);
        const float p2 = p * p, p3 = p2 * p, p4 = p2 * p2;
        T1 += p; T2 += p2; T3 += p3; T4 += p4;
        const float t = tg[r];
        np += __popc(__ballot_sync(0xffffffffu, t > 0.5f));
        P1 = fmaf(t, p,  P1);
        P2 = fmaf(t, p2, P2);
        P3 = fmaf(t, p3, P3);
        P4 = fmaf(t, p4, P4);
    }

    // Warp tree reduction (8 float accumulators; np already warp-uniform).
#pragma unroll
    for (int off = 16; off > 0; off >>= 1) {
        T1 += __shfl_xor_sync(0xffffffffu, T1, off);
        T2 += __shfl_xor_sync(0xffffffffu, T2, off);
        T3 += __shfl_xor_sync(0xffffffffu, T3, off);
        T4 += __shfl_xor_sync(0xffffffffu, T4, off);
        P1 += __shfl_xor_sync(0xffffffffu, P1, off);
        P2 += __shfl_xor_sync(0xffffffffu, P2, off);
        P3 += __shfl_xor_sync(0xffffffffu, P3, off);
        P4 += __shfl_xor_sync(0xffffffffu, P4, off);
    }

    __shared__ float s[NW][8];
    __shared__ int   sn[NW];
    if (lane == 0) {
        s[warp][0] = T1; s[warp][1] = T2; s[warp][2] = T3; s[warp][3] = T4;
        s[warp][4] = P1; s[warp][5] = P2; s[warp][6] = P3; s[warp][7] = P4;
        sn[warp] = np;
    }
    __syncthreads();
    if (tid != 0) return;

    // ---- thread 0: cross-warp sum (32 pipelined LDS) + fp32 combine ----
    float m[8];
#pragma unroll
    for (int k = 0; k < 8; k++)
        m[k] = (s[0][k] + s[1][k]) + (s[2][k] + s[3][k]);
    const int npos = (sn[0] + sn[1]) + (sn[2] + sn[3]);

    const float Pd0 = (float)npos;
    const float Td1 = m[0], Td2 = m[1], Td3 = m[2], Td4 = m[3];
    const float Pd1 = m[4], Pd2 = m[5], Pd3 = m[6], Pd4 = m[7];
    const float B0 = (float)(NROWS - npos);
    const float B1 = Td1 - Pd1, B2 = Td2 - Pd2,
                B3 = Td3 - Pd3, B4 = Td4 - Pd4;   // neg-row power sums

    const float cnt = Pd0 * B0;
    // d_m = sum_pairs (b-a)^m via binomial; signs from (-a)^k.
    const float d1 = B1 * Pd0 - B0 * Pd1;
    const float d2 = B2 * Pd0 - 2.0f * B1 * Pd1 + B0 * Pd2;
    const float d4 = B4 * Pd0 - 4.0f * B3 * Pd1 + 6.0f * B2 * Pd2
                   - 4.0f * B1 * Pd3 + B0 * Pd4;

    const float S = 0.69314718f * cnt
                  + 0.5f * d1
                  + d2 * (1.0f / 8.0f)
                  - d4 * (1.0f / 192.0f);

    const bool ok = (cnt > 0.0f);
    const float mean = ok ? (S / cnt) : 0.0f;   // in (0, 1.32)

    // Packed contribution: [count:8][valid:8][mean fixed-point 2^40:48].
    const unsigned long long fx =
        (unsigned long long)((double)mean * FXS + 0.5);
    const unsigned long long pk =
        (1ULL << 56) | ((ok ? 1ULL : 0ULL) << 48) | fx;

    const unsigned long long old = atomicAdd(&g_pack, pk);
    if ((old >> 56) == (unsigned long long)(NBLK - 1)) {
        // Last arriver: total is in hand, no fence/reload needed.
        const unsigned long long tot = old + pk;
        const double sum = (double)(tot & ((1ULL << 48) - 1)) * (1.0 / FXS);
        const double vc  = (double)((tot >> 48) & 0xFFULL);
        out[0] = (vc > 0.0) ? (float)(sum / vc) : 0.0f;
        g_pack = 0ULL;   // reset for next graph replay (all blocks done)
    }
}

extern "C" void kernel_launch(void* const* d_in, const int* in_sizes, int n_in,
                              void* d_out, int out_size)
{
    const float* logits  = (const float*)d_in[0];
    const float* targets = (const float*)d_in[1];
    float* out = (float*)d_out;

    aucm_kernel<<<NBLK, NTH>>>(logits, targets, out);
}